// round 3
// baseline (speedup 1.0000x reference)
#include <cuda_runtime.h>
#include <cuda_fp16.h>

#define NN   100000
#define EE   1600000
#define HH   64
#define FIN  14
#define GG   512
#define NBLK 391           // ceil(NN/256)

// ---------------- scratch (device globals) ----------------------------------
__device__ int   g_degc[NN];
__device__ int   g_off[NN + 1];      // CSR offsets by dst
__device__ int   g_cur[NN];          // fill cursors
__device__ int   g_bsum[512];
__device__ int   g_boff[512];
__device__ float g_dis[NN];          // deg^{-1/2}
__device__ float g_dinv[NN];         // 1/deg
__device__ __align__(16) int2   g_epack[EE];      // (src, norm bits) sorted by dst
__device__ __align__(16) float  g_aggx[NN * FIN];
__device__ __align__(16) float  g_m[NN * HH];     // fp32 m (self term)
__device__ __align__(16) __half g_mh[NN * HH];    // fp16 m (neighbor gather)
__device__ __align__(16) float  g_h[NN * HH];
__device__ int   g_gstart[GG + 1];

// ---------------- prep -------------------------------------------------------
__global__ void k_init() {
    int i = blockIdx.x * blockDim.x + threadIdx.x;
    if (i < NN) g_degc[i] = 0;
}

__global__ void k_deg(const int* __restrict__ dst) {
    int e = blockIdx.x * blockDim.x + threadIdx.x;
    if (e < EE) atomicAdd(&g_degc[dst[e]], 1);
}

__global__ void k_scanA() {
    __shared__ int s[256];
    int i = blockIdx.x * 256 + threadIdx.x;
    int v = (i < NN) ? g_degc[i] : 0;
    s[threadIdx.x] = v;
    __syncthreads();
    #pragma unroll
    for (int o = 1; o < 256; o <<= 1) {
        int t = (threadIdx.x >= o) ? s[threadIdx.x - o] : 0;
        __syncthreads();
        s[threadIdx.x] += t;
        __syncthreads();
    }
    if (i < NN) g_off[i] = s[threadIdx.x] - v;    // exclusive
    if (threadIdx.x == 255) g_bsum[blockIdx.x] = s[255];
}

__global__ void k_scanB() {
    __shared__ int s[512];
    int t = threadIdx.x;
    int v = (t < NBLK) ? g_bsum[t] : 0;
    s[t] = v;
    __syncthreads();
    #pragma unroll
    for (int o = 1; o < 512; o <<= 1) {
        int u = (t >= o) ? s[t - o] : 0;
        __syncthreads();
        s[t] += u;
        __syncthreads();
    }
    if (t < NBLK) g_boff[t] = s[t] - v;           // exclusive
}

__global__ void k_scanC() {
    int i = blockIdx.x * blockDim.x + threadIdx.x;
    if (i >= NN) return;
    int o = g_off[i] + g_boff[i >> 8];
    g_off[i] = o;
    g_cur[i] = o;
    float d = (float)(g_degc[i] + 1);
    g_dis[i]  = rsqrtf(d);
    g_dinv[i] = 1.0f / d;
    if (i == 0) g_off[NN] = EE;
}

__global__ void k_fill(const int* __restrict__ src, const int* __restrict__ dst) {
    int e = blockIdx.x * blockDim.x + threadIdx.x;
    if (e >= EE) return;
    int s = src[e], d = dst[e];
    float nrm = g_dis[s] * g_dis[d];
    int p = atomicAdd(&g_cur[d], 1);
    g_epack[p] = make_int2(s, __float_as_int(nrm));
}

__global__ void k_gb(const int* __restrict__ batch) {
    int i = blockIdx.x * blockDim.x + threadIdx.x;
    if (i >= NN) return;
    int b = batch[i];
    int pb = (i == 0) ? -1 : batch[i - 1];
    for (int g = pb + 1; g <= b; g++) g_gstart[g] = i;
    if (i == NN - 1)
        for (int g = b + 1; g <= GG; g++) g_gstart[g] = NN;
}

// ---------------- layer 1: gather-aggregate x (14-wide) then GEMM ----------
__global__ void k_agg14(const float* __restrict__ x) {
    int gidx = blockIdx.x * blockDim.x + threadIdx.x;  // NN*8
    int node = gidx >> 3, c = gidx & 7;
    if (node >= NN) return;
    int beg = g_off[node], end = g_off[node + 1];
    bool act = (c < 7);
    float ax = 0.0f, ay = 0.0f;
    for (int j = beg; j < end; j++) {
        int2 p = g_epack[j];
        float nrm = __int_as_float(p.y);
        if (act) {
            float2 xv = *(const float2*)&x[p.x * FIN + c * 2];
            ax += nrm * xv.x;
            ay += nrm * xv.y;
        }
    }
    if (act) {
        float dv = g_dinv[node];
        float2 xs = *(const float2*)&x[node * FIN + c * 2];
        ax += dv * xs.x;
        ay += dv * xs.y;
        *(float2*)&g_aggx[node * FIN + c * 2] = make_float2(ax, ay);
    }
}

__global__ void k_gemm1(const float* __restrict__ W1, const float* __restrict__ b1) {
    int idx = blockIdx.x * blockDim.x + threadIdx.x;
    if (idx >= NN * HH) return;
    int i = idx >> 6, j = idx & 63;
    float acc = b1[j];
    #pragma unroll
    for (int k = 0; k < FIN; k++)
        acc += g_aggx[i * FIN + k] * W1[k * HH + j];
    g_h[idx] = fmaxf(acc, 0.0f);   // relu applied; h holds relu'ed activations
}

// ---------------- layers 2..5 ------------------------------------------------
// m = h @ W   (h already relu'ed); writes fp32 g_m and fp16 g_mh
__global__ void __launch_bounds__(128)
k_gemm64(const float* __restrict__ W) {
    __shared__ float ws[64 * 64];
    __shared__ float hs[64 * 68];    // transposed [k][r], padded
    int tid = threadIdx.x;
    int row0 = blockIdx.x * 64;

    #pragma unroll
    for (int t = 0; t < 32; t++)
        ws[t * 128 + tid] = W[t * 128 + tid];

    #pragma unroll
    for (int t = 0; t < 32; t++) {
        int idx = t * 128 + tid;
        int r = idx >> 6, k = idx & 63;
        int row = row0 + r;
        hs[k * 68 + r] = (row < NN) ? g_h[row * 64 + k] : 0.0f;
    }
    __syncthreads();

    int tx = tid & 7, ty = tid >> 3;          // 8x16 threads, 4 rows x 8 cols each
    float acc[4][8];
    #pragma unroll
    for (int i = 0; i < 4; i++)
        #pragma unroll
        for (int j = 0; j < 8; j++) acc[i][j] = 0.0f;

    #pragma unroll 8
    for (int k = 0; k < 64; k++) {
        float4 a  = *(const float4*)&hs[k * 68 + ty * 4];
        float4 w0 = *(const float4*)&ws[k * 64 + tx * 8];
        float4 w1 = *(const float4*)&ws[k * 64 + tx * 8 + 4];
        float av[4] = {a.x, a.y, a.z, a.w};
        float wv[8] = {w0.x, w0.y, w0.z, w0.w, w1.x, w1.y, w1.z, w1.w};
        #pragma unroll
        for (int i = 0; i < 4; i++)
            #pragma unroll
            for (int j = 0; j < 8; j++)
                acc[i][j] += av[i] * wv[j];
    }

    #pragma unroll
    for (int i = 0; i < 4; i++) {
        int row = row0 + ty * 4 + i;
        if (row < NN) {
            *(float4*)&g_m[row * 64 + tx * 8]     = make_float4(acc[i][0], acc[i][1], acc[i][2], acc[i][3]);
            *(float4*)&g_m[row * 64 + tx * 8 + 4] = make_float4(acc[i][4], acc[i][5], acc[i][6], acc[i][7]);
            __half2 h0 = __floats2half2_rn(acc[i][0], acc[i][1]);
            __half2 h1 = __floats2half2_rn(acc[i][2], acc[i][3]);
            __half2 h2 = __floats2half2_rn(acc[i][4], acc[i][5]);
            __half2 h3 = __floats2half2_rn(acc[i][6], acc[i][7]);
            uint4 pk;
            pk.x = *(unsigned*)&h0; pk.y = *(unsigned*)&h1;
            pk.z = *(unsigned*)&h2; pk.w = *(unsigned*)&h3;
            *(uint4*)&g_mh[row * 64 + tx * 8] = pk;
        }
    }
}

// h = relu( gather(norm * mh[src]) + m*dinv + b )   — 16 lanes per node
// neighbor gather in fp16 (8B/lane), self term fp32
__global__ void __launch_bounds__(256)
k_agg64(const float* __restrict__ b) {
    int t = threadIdx.x;
    int node = blockIdx.x * 16 + (t >> 4);
    int c = t & 15;                  // lane covers columns c*4 .. c*4+3
    if (node >= NN) return;
    int beg = g_off[node], end = g_off[node + 1];

    float4 acc = make_float4(0.f, 0.f, 0.f, 0.f);
    int j = beg;
    for (; j + 1 < end; j += 2) {
        int2 p0 = g_epack[j];
        int2 p1 = g_epack[j + 1];
        float n0 = __int_as_float(p0.y);
        float n1 = __int_as_float(p1.y);
        uint2 r0 = *(const uint2*)&g_mh[p0.x * 64 + c * 4];
        uint2 r1 = *(const uint2*)&g_mh[p1.x * 64 + c * 4];
        float2 a0 = __half22float2(*(__half2*)&r0.x);
        float2 a1 = __half22float2(*(__half2*)&r0.y);
        float2 b0 = __half22float2(*(__half2*)&r1.x);
        float2 b1 = __half22float2(*(__half2*)&r1.y);
        acc.x += n0 * a0.x + n1 * b0.x;
        acc.y += n0 * a0.y + n1 * b0.y;
        acc.z += n0 * a1.x + n1 * b1.x;
        acc.w += n0 * a1.y + n1 * b1.y;
    }
    if (j < end) {
        int2 p = g_epack[j];
        float n = __int_as_float(p.y);
        uint2 r0 = *(const uint2*)&g_mh[p.x * 64 + c * 4];
        float2 a0 = __half22float2(*(__half2*)&r0.x);
        float2 a1 = __half22float2(*(__half2*)&r0.y);
        acc.x += n * a0.x; acc.y += n * a0.y;
        acc.z += n * a1.x; acc.w += n * a1.y;
    }

    float dv = g_dinv[node];
    float4 mv = *(const float4*)&g_m[node * 64 + c * 4];
    float4 bb = *(const float4*)&b[c * 4];
    float4 o;
    o.x = fmaxf(acc.x + dv * mv.x + bb.x, 0.0f);
    o.y = fmaxf(acc.y + dv * mv.y + bb.y, 0.0f);
    o.z = fmaxf(acc.z + dv * mv.z + bb.z, 0.0f);
    o.w = fmaxf(acc.w + dv * mv.w + bb.w, 0.0f);
    *(float4*)&g_h[node * 64 + c * 4] = o;
}

// ---------------- pooling + head (fused), one block per graph ---------------
__global__ void __launch_bounds__(256)
k_pool(const float* __restrict__ Wl, const float* __restrict__ bl,
       float* __restrict__ out) {
    int g = blockIdx.x;
    int s = g_gstart[g], e = g_gstart[g + 1];
    int tid = threadIdx.x;
    int j = tid & 63, r = tid >> 6;

    float mx = 0.0f;    // relu'ed values >= 0; nonempty graphs -> max >= 0
    for (int i = s + r; i < e; i += 4)
        mx = fmaxf(mx, g_h[i * 64 + j]);

    __shared__ float sm[256];
    sm[tid] = mx;
    __syncthreads();
    if (tid < 64) {
        float p = fmaxf(fmaxf(sm[tid], sm[tid + 64]),
                        fmaxf(sm[tid + 128], sm[tid + 192]));
        sm[tid]      = p * Wl[tid * 2];
        sm[tid + 64] = p * Wl[tid * 2 + 1];
    }
    __syncthreads();
    #pragma unroll
    for (int o = 32; o >= 1; o >>= 1) {
        if (tid < o) {
            sm[tid]      += sm[tid + o];
            sm[tid + 64] += sm[tid + 64 + o];
        }
        __syncthreads();
    }
    if (tid == 0) {
        out[g * 2]     = sm[0]  + bl[0];
        out[g * 2 + 1] = sm[64] + bl[1];
    }
}

// ---------------- launch -----------------------------------------------------
extern "C" void kernel_launch(void* const* d_in, const int* in_sizes, int n_in,
                              void* d_out, int out_size) {
    const float* x  = (const float*)d_in[0];
    const int*   ei = (const int*)d_in[13];
    const int*   bt = (const int*)d_in[14];
    const int* src = ei;
    const int* dst = ei + EE;
    float* out = (float*)d_out;

    const int T = 256;
    k_init <<<NBLK, T>>>();
    k_deg  <<<(EE + T - 1) / T, T>>>(dst);
    k_scanA<<<NBLK, T>>>();
    k_scanB<<<1, 512>>>();
    k_scanC<<<NBLK, T>>>();
    k_fill <<<(EE + T - 1) / T, T>>>(src, dst);
    k_gb   <<<NBLK, T>>>(bt);

    // layer 1
    k_agg14<<<(NN * 8 + T - 1) / T, T>>>(x);
    k_gemm1<<<(NN * HH + T - 1) / T, T>>>((const float*)d_in[1], (const float*)d_in[2]);

    // layers 2..5
    for (int l = 0; l < 4; l++) {
        const float* W = (const float*)d_in[3 + 2 * l];
        const float* b = (const float*)d_in[4 + 2 * l];
        k_gemm64<<<(NN + 63) / 64, 128>>>(W);
        k_agg64 <<<(NN + 15) / 16, 256>>>(b);
    }

    k_pool<<<GG, 256>>>((const float*)d_in[11], (const float*)d_in[12], out);
}

// round 4
// speedup vs baseline: 1.1499x; 1.1499x over previous
#include <cuda_runtime.h>
#include <cuda_fp16.h>

#define NN   100000
#define EE   1600000
#define HH   64
#define FIN  14
#define GG   512
#define NBLK 391           // ceil(NN/256)

// ---------------- scratch (device globals) ----------------------------------
__device__ int   g_degc[NN];
__device__ int   g_off[NN + 1];      // CSR offsets by dst
__device__ int   g_cur[NN];          // fill cursors
__device__ int   g_bsum[512];
__device__ int   g_boff[512];
__device__ float g_dis[NN];          // deg^{-1/2}
__device__ float g_dinv[NN];         // 1/deg
__device__ __align__(16) int2   g_epack[EE];      // (src, norm bits) sorted by dst
__device__ __align__(16) float  g_aggx[NN * FIN];
__device__ __align__(16) __half g_mh[NN * HH];    // fp16 m = h @ W
__device__ __align__(16) float  g_h[NN * HH];
__device__ int   g_gstart[GG + 1];

// ---------------- prep -------------------------------------------------------
__global__ void k_deg(const int* __restrict__ dst) {
    int e = blockIdx.x * blockDim.x + threadIdx.x;
    if (e < EE) atomicAdd(&g_degc[dst[e]], 1);
}

__global__ void k_scanA() {
    __shared__ int s[256];
    int i = blockIdx.x * 256 + threadIdx.x;
    int v = (i < NN) ? g_degc[i] : 0;
    s[threadIdx.x] = v;
    __syncthreads();
    #pragma unroll
    for (int o = 1; o < 256; o <<= 1) {
        int t = (threadIdx.x >= o) ? s[threadIdx.x - o] : 0;
        __syncthreads();
        s[threadIdx.x] += t;
        __syncthreads();
    }
    if (i < NN) g_off[i] = s[threadIdx.x] - v;    // exclusive
    if (threadIdx.x == 255) g_bsum[blockIdx.x] = s[255];
}

__global__ void k_scanB() {
    __shared__ int s[512];
    int t = threadIdx.x;
    int v = (t < NBLK) ? g_bsum[t] : 0;
    s[t] = v;
    __syncthreads();
    #pragma unroll
    for (int o = 1; o < 512; o <<= 1) {
        int u = (t >= o) ? s[t - o] : 0;
        __syncthreads();
        s[t] += u;
        __syncthreads();
    }
    if (t < NBLK) g_boff[t] = s[t] - v;           // exclusive
}

// offsets + dinv + graph boundaries (merged)
__global__ void k_scanC(const int* __restrict__ batch) {
    int i = blockIdx.x * blockDim.x + threadIdx.x;
    if (i >= NN) return;
    int o = g_off[i] + g_boff[i >> 8];
    g_off[i] = o;
    g_cur[i] = o;
    float d = (float)(g_degc[i] + 1);
    g_dis[i]  = rsqrtf(d);
    g_dinv[i] = 1.0f / d;
    if (i == 0) g_off[NN] = EE;
    int b = batch[i];
    int pb = (i == 0) ? -1 : batch[i - 1];
    for (int g = pb + 1; g <= b; g++) g_gstart[g] = i;
    if (i == NN - 1)
        for (int g = b + 1; g <= GG; g++) g_gstart[g] = NN;
}

__global__ void k_fill(const int* __restrict__ src, const int* __restrict__ dst) {
    int e = blockIdx.x * blockDim.x + threadIdx.x;
    if (e >= EE) return;
    int s = src[e], d = dst[e];
    float nrm = g_dis[s] * g_dis[d];
    int p = atomicAdd(&g_cur[d], 1);
    g_epack[p] = make_int2(s, __float_as_int(nrm));
}

// ---------------- layer 1: gather-aggregate x (14-wide) then GEMM ----------
__global__ void k_agg14(const float* __restrict__ x) {
    int gidx = blockIdx.x * blockDim.x + threadIdx.x;  // NN*8
    int node = gidx >> 3, c = gidx & 7;
    if (node >= NN) return;
    int beg = g_off[node], end = g_off[node + 1];
    bool act = (c < 7);
    float ax = 0.0f, ay = 0.0f;
    for (int j = beg; j < end; j++) {
        int2 p = g_epack[j];
        float nrm = __int_as_float(p.y);
        if (act) {
            float2 xv = *(const float2*)&x[p.x * FIN + c * 2];
            ax += nrm * xv.x;
            ay += nrm * xv.y;
        }
    }
    if (act) {
        float dv = g_dinv[node];
        float2 xs = *(const float2*)&x[node * FIN + c * 2];
        ax += dv * xs.x;
        ay += dv * xs.y;
        *(float2*)&g_aggx[node * FIN + c * 2] = make_float2(ax, ay);
    }
}

__global__ void k_gemm1(const float* __restrict__ W1, const float* __restrict__ b1) {
    int idx = blockIdx.x * blockDim.x + threadIdx.x;
    if (idx >= NN * HH) return;
    int i = idx >> 6, j = idx & 63;
    float acc = b1[j];
    #pragma unroll
    for (int k = 0; k < FIN; k++)
        acc += g_aggx[i * FIN + k] * W1[k * HH + j];
    g_h[idx] = fmaxf(acc, 0.0f);   // relu applied; h holds relu'ed activations
}

// ---------------- layers 2..5 ------------------------------------------------
// m = h @ W   (h already relu'ed); writes fp16 g_mh only
__global__ void __launch_bounds__(128)
k_gemm64(const float* __restrict__ W) {
    __shared__ float ws[64 * 64];
    __shared__ float hs[64 * 68];    // transposed [k][r], padded
    int tid = threadIdx.x;
    int row0 = blockIdx.x * 64;

    #pragma unroll
    for (int t = 0; t < 32; t++)
        ws[t * 128 + tid] = W[t * 128 + tid];

    #pragma unroll
    for (int t = 0; t < 32; t++) {
        int idx = t * 128 + tid;
        int r = idx >> 6, k = idx & 63;
        int row = row0 + r;
        hs[k * 68 + r] = (row < NN) ? g_h[row * 64 + k] : 0.0f;
    }
    __syncthreads();

    int tx = tid & 7, ty = tid >> 3;          // 8x16 threads, 4 rows x 8 cols each
    float acc[4][8];
    #pragma unroll
    for (int i = 0; i < 4; i++)
        #pragma unroll
        for (int j = 0; j < 8; j++) acc[i][j] = 0.0f;

    #pragma unroll 8
    for (int k = 0; k < 64; k++) {
        float4 a  = *(const float4*)&hs[k * 68 + ty * 4];
        float4 w0 = *(const float4*)&ws[k * 64 + tx * 8];
        float4 w1 = *(const float4*)&ws[k * 64 + tx * 8 + 4];
        float av[4] = {a.x, a.y, a.z, a.w};
        float wv[8] = {w0.x, w0.y, w0.z, w0.w, w1.x, w1.y, w1.z, w1.w};
        #pragma unroll
        for (int i = 0; i < 4; i++)
            #pragma unroll
            for (int j = 0; j < 8; j++)
                acc[i][j] += av[i] * wv[j];
    }

    #pragma unroll
    for (int i = 0; i < 4; i++) {
        int row = row0 + ty * 4 + i;
        if (row < NN) {
            __half2 h0 = __floats2half2_rn(acc[i][0], acc[i][1]);
            __half2 h1 = __floats2half2_rn(acc[i][2], acc[i][3]);
            __half2 h2 = __floats2half2_rn(acc[i][4], acc[i][5]);
            __half2 h3 = __floats2half2_rn(acc[i][6], acc[i][7]);
            uint4 pk;
            pk.x = *(unsigned*)&h0; pk.y = *(unsigned*)&h1;
            pk.z = *(unsigned*)&h2; pk.w = *(unsigned*)&h3;
            *(uint4*)&g_mh[row * 64 + tx * 8] = pk;
        }
    }
}

// h = relu( gather(norm * mh[src]) + mh[node]*dinv + b )
// 8 lanes per node, each lane covers 8 columns (16B fp16 per load)
__global__ void __launch_bounds__(256)
k_agg64(const float* __restrict__ b) {
    int t = threadIdx.x;
    int node = blockIdx.x * 32 + (t >> 3);
    int c = t & 7;                    // columns c*8 .. c*8+7
    if (node >= NN) return;
    int beg = g_off[node], end = g_off[node + 1];

    float acc[8];
    #pragma unroll
    for (int i = 0; i < 8; i++) acc[i] = 0.0f;

    int j = beg;
    for (; j + 1 < end; j += 2) {
        int2 p0 = g_epack[j];
        int2 p1 = g_epack[j + 1];
        uint4 r0 = *(const uint4*)&g_mh[p0.x * 64 + c * 8];
        uint4 r1 = *(const uint4*)&g_mh[p1.x * 64 + c * 8];
        float n0 = __int_as_float(p0.y);
        float n1 = __int_as_float(p1.y);
        const unsigned* u0 = &r0.x;
        const unsigned* u1 = &r1.x;
        #pragma unroll
        for (int q = 0; q < 4; q++) {
            float2 a = __half22float2(*(__half2*)&u0[q]);
            float2 bq = __half22float2(*(__half2*)&u1[q]);
            acc[q * 2]     += n0 * a.x + n1 * bq.x;
            acc[q * 2 + 1] += n0 * a.y + n1 * bq.y;
        }
    }
    if (j < end) {
        int2 p = g_epack[j];
        float n = __int_as_float(p.y);
        uint4 r0 = *(const uint4*)&g_mh[p.x * 64 + c * 8];
        const unsigned* u0 = &r0.x;
        #pragma unroll
        for (int q = 0; q < 4; q++) {
            float2 a = __half22float2(*(__half2*)&u0[q]);
            acc[q * 2]     += n * a.x;
            acc[q * 2 + 1] += n * a.y;
        }
    }

    float dv = g_dinv[node];
    uint4 rs = *(const uint4*)&g_mh[node * 64 + c * 8];
    const unsigned* us = &rs.x;
    float4 b0 = *(const float4*)&b[c * 8];
    float4 b1 = *(const float4*)&b[c * 8 + 4];
    float bb[8] = {b0.x, b0.y, b0.z, b0.w, b1.x, b1.y, b1.z, b1.w};
    float o[8];
    #pragma unroll
    for (int q = 0; q < 4; q++) {
        float2 s = __half22float2(*(__half2*)&us[q]);
        o[q * 2]     = fmaxf(acc[q * 2]     + dv * s.x + bb[q * 2],     0.0f);
        o[q * 2 + 1] = fmaxf(acc[q * 2 + 1] + dv * s.y + bb[q * 2 + 1], 0.0f);
    }
    *(float4*)&g_h[node * 64 + c * 8]     = make_float4(o[0], o[1], o[2], o[3]);
    *(float4*)&g_h[node * 64 + c * 8 + 4] = make_float4(o[4], o[5], o[6], o[7]);
}

// ---------------- pooling + head (fused), one block per graph ---------------
__global__ void __launch_bounds__(256)
k_pool(const float* __restrict__ Wl, const float* __restrict__ bl,
       float* __restrict__ out) {
    int g = blockIdx.x;
    int s = g_gstart[g], e = g_gstart[g + 1];
    int tid = threadIdx.x;
    int j = tid & 63, r = tid >> 6;

    float mx = 0.0f;    // relu'ed values >= 0; nonempty graphs -> max >= 0
    for (int i = s + r; i < e; i += 4)
        mx = fmaxf(mx, g_h[i * 64 + j]);

    __shared__ float sm[256];
    sm[tid] = mx;
    __syncthreads();
    if (tid < 64) {
        float p = fmaxf(fmaxf(sm[tid], sm[tid + 64]),
                        fmaxf(sm[tid + 128], sm[tid + 192]));
        sm[tid]      = p * Wl[tid * 2];
        sm[tid + 64] = p * Wl[tid * 2 + 1];
    }
    __syncthreads();
    #pragma unroll
    for (int o = 32; o >= 1; o >>= 1) {
        if (tid < o) {
            sm[tid]      += sm[tid + o];
            sm[tid + 64] += sm[tid + 64 + o];
        }
        __syncthreads();
    }
    if (tid == 0) {
        out[g * 2]     = sm[0]  + bl[0];
        out[g * 2 + 1] = sm[64] + bl[1];
    }
}

// ---------------- launch -----------------------------------------------------
extern "C" void kernel_launch(void* const* d_in, const int* in_sizes, int n_in,
                              void* d_out, int out_size) {
    const float* x  = (const float*)d_in[0];
    const int*   ei = (const int*)d_in[13];
    const int*   bt = (const int*)d_in[14];
    const int* src = ei;
    const int* dst = ei + EE;
    float* out = (float*)d_out;

    void* degc_ptr = nullptr;
    cudaGetSymbolAddress(&degc_ptr, g_degc);
    cudaMemsetAsync(degc_ptr, 0, NN * sizeof(int));

    const int T = 256;
    k_deg  <<<(EE + T - 1) / T, T>>>(dst);
    k_scanA<<<NBLK, T>>>();
    k_scanB<<<1, 512>>>();
    k_scanC<<<NBLK, T>>>(bt);
    k_fill <<<(EE + T - 1) / T, T>>>(src, dst);

    // layer 1
    k_agg14<<<(NN * 8 + T - 1) / T, T>>>(x);
    k_gemm1<<<(NN * HH + T - 1) / T, T>>>((const float*)d_in[1], (const float*)d_in[2]);

    // layers 2..5
    for (int l = 0; l < 4; l++) {
        const float* W = (const float*)d_in[3 + 2 * l];
        const float* b = (const float*)d_in[4 + 2 * l];
        k_gemm64<<<(NN + 63) / 64, 128>>>(W);
        k_agg64 <<<(NN + 31) / 32, 256>>>(b);
    }

    k_pool<<<GG, 256>>>((const float*)d_in[11], (const float*)d_in[12], out);
}